// round 6
// baseline (speedup 1.0000x reference)
#include <cuda_runtime.h>
#include <cuda_fp16.h>
#include <cstdint>

// Problem constants (C=32,H=32,W=32,KS=3, B=32)
constexpr int NDIM = 32 * 32 * 32 + 1;   // 32769
constexpr int KDIM = 32 * 3 * 3;         // 288
constexpr int BDIM = 32;

// x transposed to [N, B] in fp16: each row is 64 B, so one LDG.128 with
// 4-lane groups gathers EIGHT different rows per instruction.
__device__ __half g_xT[(size_t)NDIM * BDIM];

// ---------------------------------------------------------------------------
// Kernel 1: transpose + fp16-convert x [B, N] -> x_T [N, B].
// ---------------------------------------------------------------------------
__global__ __launch_bounds__(1024) void transpose_kernel(const float* __restrict__ x)
{
    __shared__ float tile[32][33];
    const int n0 = blockIdx.x * 32;
    const int tx = threadIdx.x;
    const int ty = threadIdx.y;

    const int n_load = n0 + tx;
    if (n_load < NDIM)
        tile[ty][tx] = x[(size_t)ty * NDIM + n_load];
    __syncthreads();

    const int n_store = n0 + ty;
    if (n_store < NDIM)
        g_xT[(size_t)n_store * BDIM + tx] = __float2half(tile[tx][ty]);
}

// ---------------------------------------------------------------------------
// Kernel 2 (persistent): each warp handles row n; grid-stride over row-blocks.
//   g = lane>>2 : lane group; quad = lane&3 : 16B slice of a 64B fp16 row.
// k-ownership: group g owns k = 32q + 4g + {0..3}, q = 0..8.
//   feed: ONE int4 + ONE float4 per group per q -> 8 groups span one 128B
//         line -> 1 wavefront per 32 k's per array (18 feed wf/row vs 72).
//   gather: 4 LDG.128 per group per q (one per col), 8 rows/instruction.
// Feed for q+1 is prefetched while q's gathers convert; full unroll lets
// ptxas overlap gather issue across q's within the 64-reg budget.
// ---------------------------------------------------------------------------
constexpr int WARPS_PER_BLOCK = 8;
constexpr int NBLK = (NDIM + WARPS_PER_BLOCK - 1) / WARPS_PER_BLOCK;  // 4097
constexpr int GRID = 148 * 4;                                          // 592
constexpr int QCNT = KDIM / 32;                                        // 9

__global__ __launch_bounds__(WARPS_PER_BLOCK * 32, 4)
void gather_dot_kernel(const float* __restrict__ vals,
                       const int*   __restrict__ cols,
                       float*       __restrict__ out)
{
    __shared__ float s_acc[WARPS_PER_BLOCK][33];   // [n_off][b], padded

    const int w    = threadIdx.x >> 5;
    const int lane = threadIdx.x & 31;
    const int g    = lane >> 2;   // group 0..7
    const int quad = lane & 3;    // 16B slice -> b = quad*8 .. quad*8+7

    for (int rb = blockIdx.x; rb < NBLK; rb += GRID) {
        const int n = rb * WARPS_PER_BLOCK + w;

        float acc[8] = {0.f, 0.f, 0.f, 0.f, 0.f, 0.f, 0.f, 0.f};

        if (n < NDIM) {
            // group-g feed pointers: int4/float4 index q*8 + g
            const int4*   cp = (const int4*)  (cols + (size_t)n * KDIM) + g;
            const float4* vp = (const float4*)(vals + (size_t)n * KDIM) + g;
            const char*   xb = (const char*)g_xT + quad * 16;

            int4   c = __ldg(cp);          // feed q=0 (1 wf across warp)
            float4 v = __ldg(vp);

            #pragma unroll
            for (int q = 0; q < QCNT; ++q) {
                // 4 independent gathers for this q
                uint4 h0 = __ldg((const uint4*)(xb + ((size_t)(unsigned)c.x << 6)));
                uint4 h1 = __ldg((const uint4*)(xb + ((size_t)(unsigned)c.y << 6)));
                uint4 h2 = __ldg((const uint4*)(xb + ((size_t)(unsigned)c.z << 6)));
                uint4 h3 = __ldg((const uint4*)(xb + ((size_t)(unsigned)c.w << 6)));
                float4 vc = v;

                // prefetch feed for q+1 while the gathers are in flight
                if (q + 1 < QCNT) {
                    c = __ldg(cp + (q + 1) * 8);
                    v = __ldg(vp + (q + 1) * 8);
                }

                // convert + accumulate (8 b's per h)
                {
                    float2 f0 = __half22float2(*(const __half2*)&h0.x);
                    float2 f1 = __half22float2(*(const __half2*)&h0.y);
                    float2 f2 = __half22float2(*(const __half2*)&h0.z);
                    float2 f3 = __half22float2(*(const __half2*)&h0.w);
                    acc[0] = fmaf(vc.x, f0.x, acc[0]); acc[1] = fmaf(vc.x, f0.y, acc[1]);
                    acc[2] = fmaf(vc.x, f1.x, acc[2]); acc[3] = fmaf(vc.x, f1.y, acc[3]);
                    acc[4] = fmaf(vc.x, f2.x, acc[4]); acc[5] = fmaf(vc.x, f2.y, acc[5]);
                    acc[6] = fmaf(vc.x, f3.x, acc[6]); acc[7] = fmaf(vc.x, f3.y, acc[7]);
                }
                {
                    float2 f0 = __half22float2(*(const __half2*)&h1.x);
                    float2 f1 = __half22float2(*(const __half2*)&h1.y);
                    float2 f2 = __half22float2(*(const __half2*)&h1.z);
                    float2 f3 = __half22float2(*(const __half2*)&h1.w);
                    acc[0] = fmaf(vc.y, f0.x, acc[0]); acc[1] = fmaf(vc.y, f0.y, acc[1]);
                    acc[2] = fmaf(vc.y, f1.x, acc[2]); acc[3] = fmaf(vc.y, f1.y, acc[3]);
                    acc[4] = fmaf(vc.y, f2.x, acc[4]); acc[5] = fmaf(vc.y, f2.y, acc[5]);
                    acc[6] = fmaf(vc.y, f3.x, acc[6]); acc[7] = fmaf(vc.y, f3.y, acc[7]);
                }
                {
                    float2 f0 = __half22float2(*(const __half2*)&h2.x);
                    float2 f1 = __half22float2(*(const __half2*)&h2.y);
                    float2 f2 = __half22float2(*(const __half2*)&h2.z);
                    float2 f3 = __half22float2(*(const __half2*)&h2.w);
                    acc[0] = fmaf(vc.z, f0.x, acc[0]); acc[1] = fmaf(vc.z, f0.y, acc[1]);
                    acc[2] = fmaf(vc.z, f1.x, acc[2]); acc[3] = fmaf(vc.z, f1.y, acc[3]);
                    acc[4] = fmaf(vc.z, f2.x, acc[4]); acc[5] = fmaf(vc.z, f2.y, acc[5]);
                    acc[6] = fmaf(vc.z, f3.x, acc[6]); acc[7] = fmaf(vc.z, f3.y, acc[7]);
                }
                {
                    float2 f0 = __half22float2(*(const __half2*)&h3.x);
                    float2 f1 = __half22float2(*(const __half2*)&h3.y);
                    float2 f2 = __half22float2(*(const __half2*)&h3.z);
                    float2 f3 = __half22float2(*(const __half2*)&h3.w);
                    acc[0] = fmaf(vc.w, f0.x, acc[0]); acc[1] = fmaf(vc.w, f0.y, acc[1]);
                    acc[2] = fmaf(vc.w, f1.x, acc[2]); acc[3] = fmaf(vc.w, f1.y, acc[3]);
                    acc[4] = fmaf(vc.w, f2.x, acc[4]); acc[5] = fmaf(vc.w, f2.y, acc[5]);
                    acc[6] = fmaf(vc.w, f3.x, acc[6]); acc[7] = fmaf(vc.w, f3.y, acc[7]);
                }
            }
        }

        // Butterfly-reduce over the 8 groups (lane bits [2:4]).
        #pragma unroll
        for (int s = 4; s < 32; s <<= 1) {
            #pragma unroll
            for (int j = 0; j < 8; ++j)
                acc[j] += __shfl_xor_sync(0xffffffffu, acc[j], s);
        }

        // Lanes 0..3 hold final sums for b = quad*8 + j.
        if (lane < 4) {
            #pragma unroll
            for (int j = 0; j < 8; ++j)
                s_acc[w][lane * 8 + j] = acc[j];
        }
        __syncthreads();

        // Sector-coalesced store: thread t -> b = t/8, j = t%8.
        const int b  = threadIdx.x >> 3;
        const int j  = threadIdx.x & 7;
        const int nn = rb * WARPS_PER_BLOCK + j;
        if (nn < NDIM)
            out[(size_t)b * NDIM + nn] = s_acc[j][b];
        __syncthreads();   // protect s_acc reuse next iteration
    }
}

// ---------------------------------------------------------------------------
// kernel_launch: inputs per metadata order: x_affine (f32), vals (f32), cols (i32)
// ---------------------------------------------------------------------------
extern "C" void kernel_launch(void* const* d_in, const int* in_sizes, int n_in,
                              void* d_out, int out_size)
{
    const float* x    = (const float*)d_in[0];
    const float* vals = (const float*)d_in[1];
    const int*   cols = (const int*)  d_in[2];
    float*       out  = (float*)d_out;

    (void)in_sizes; (void)n_in; (void)out_size;

    {
        dim3 block(32, 32);
        dim3 grid((NDIM + 31) / 32);
        transpose_kernel<<<grid, block>>>(x);
    }
    {
        gather_dot_kernel<<<GRID, WARPS_PER_BLOCK * 32>>>(vals, cols, out);
    }
}